// round 5
// baseline (speedup 1.0000x reference)
#include <cuda_runtime.h>
#include <cuda_bf16.h>
#include <math.h>

#define Ll 4096
#define Dd 64
#define BH 32
#define NBLK 64
#define TSEL 6
#define SCALE 0.125f
#define P68 68
#define PJ 132      // floats per d2-row in pair-packed (T2) buffers

typedef unsigned long long ull;

__device__ __forceinline__ ull dup2(float x) {
    ull r; asm("mov.b64 %0, {%1, %1};" : "=l"(r) : "f"(x)); return r;
}
__device__ __forceinline__ void ffma2(ull& d, ull a, ull b) {
    asm("fma.rn.f32x2 %0, %1, %2, %3;" : "=l"(d) : "l"(a), "l"(b), "l"(d));
}
__device__ __forceinline__ ull mul2(ull a, ull b) {
    ull r; asm("mul.rn.f32x2 %0, %1, %2;" : "=l"(r) : "l"(a), "l"(b)); return r;
}
__device__ __forceinline__ float2 unpk(ull v) {
    float2 f; asm("mov.b64 {%0, %1}, %2;" : "=f"(f.x), "=f"(f.y) : "l"(v)); return f;
}

__device__ float g_qb[BH * NBLK * Dd];
__device__ float g_kb[BH * NBLK * Dd];
__device__ int   g_lut[BH * NBLK * TSEL];
// g_kv per (bh,kb): 4096 floats in pair-interleaved layout:
//   g_kv[blk][ (d>>1)*128 + 2*e + (d&1) ] = kv[d][e]
__device__ float g_kv[(size_t)BH * NBLK * Dd * Dd];
__device__ float g_z[BH * NBLK * Dd];
__device__ float g_kvtot[BH * Dd * Dd];   // same interleaved layout
__device__ float g_ztot[BH * Dd];

// outer-product GEMM step (k_kvz only)
#define GSTEP(Abase, Bbase, ACC)                                        \
    {                                                                   \
        float4 af = *(const float4*)(Abase);                            \
        ulonglong2 bp = *(const ulonglong2*)(Bbase);                    \
        ull a0 = dup2(af.x), a1 = dup2(af.y), a2 = dup2(af.z), a3 = dup2(af.w); \
        ffma2(ACC[0], a0, bp.x); ffma2(ACC[1], a0, bp.y);               \
        ffma2(ACC[2], a1, bp.x); ffma2(ACC[3], a1, bp.y);               \
        ffma2(ACC[4], a2, bp.x); ffma2(ACC[5], a2, bp.y);               \
        ffma2(ACC[6], a3, bp.x); ffma2(ACC[7], a3, bp.y);               \
    }

// dot-packed GEMM over 32 d-pairs; 8x2 tile; ACC = 16 ull pair-accumulators
#define DGEMM(Ab, Bb, ACC)                                              \
    _Pragma("unroll 8")                                                 \
    for (int d2 = 0; d2 < 32; d2++) {                                   \
        const float* Ar = (Ab) + d2 * PJ + 16 * tr;                     \
        const float* Br = (Bb) + d2 * PJ + 4 * tc;                      \
        ulonglong2 a01 = *(const ulonglong2*)(Ar);                      \
        ulonglong2 a23 = *(const ulonglong2*)(Ar + 4);                  \
        ulonglong2 a45 = *(const ulonglong2*)(Ar + 8);                  \
        ulonglong2 a67 = *(const ulonglong2*)(Ar + 12);                 \
        ulonglong2 bb2 = *(const ulonglong2*)(Br);                      \
        ffma2(ACC[0],  a01.x, bb2.x); ffma2(ACC[1],  a01.x, bb2.y);     \
        ffma2(ACC[2],  a01.y, bb2.x); ffma2(ACC[3],  a01.y, bb2.y);     \
        ffma2(ACC[4],  a23.x, bb2.x); ffma2(ACC[5],  a23.x, bb2.y);     \
        ffma2(ACC[6],  a23.y, bb2.x); ffma2(ACC[7],  a23.y, bb2.y);     \
        ffma2(ACC[8],  a45.x, bb2.x); ffma2(ACC[9],  a45.x, bb2.y);     \
        ffma2(ACC[10], a45.y, bb2.x); ffma2(ACC[11], a45.y, bb2.y);     \
        ffma2(ACC[12], a67.x, bb2.x); ffma2(ACC[13], a67.x, bb2.y);     \
        ffma2(ACC[14], a67.y, bb2.x); ffma2(ACC[15], a67.y, bb2.y);     \
    }

// ---------------------------------------------------------------------------
__global__ void k_blockmean(const float* __restrict__ q, const float* __restrict__ k) {
    int blk = blockIdx.x;
    const float* src = blockIdx.y ? k : q;
    float* dst = blockIdx.y ? g_kb : g_qb;
    int d = threadIdx.x;
    const float* base = src + (size_t)blk * 64 * Dd + d;
    float s = 0.f;
#pragma unroll
    for (int r = 0; r < 64; r++) s += base[r * Dd];
    dst[blk * Dd + d] = s * (1.f / 64.f);
}

// ---------------------------------------------------------------------------
__global__ void k_topk() {
    int bh = blockIdx.x >> 6, qb = blockIdx.x & 63;
    __shared__ float qrow[Dd];
    __shared__ float sc[NBLK];
    int t = threadIdx.x;
    qrow[t] = g_qb[(bh * NBLK + qb) * Dd + t];
    __syncthreads();
    const float* kb = g_kb + (bh * NBLK + t) * Dd;
    float acc = 0.f;
#pragma unroll
    for (int d = 0; d < Dd; d++) acc += qrow[d] * kb[d];
    sc[t] = acc * SCALE;
    __syncthreads();
    if (t == 0) {
        for (int s = 0; s < TSEL; s++) {
            float best = -3.4e38f; int bi = 0;
            for (int j = 0; j < NBLK; j++)
                if (sc[j] > best) { best = sc[j]; bi = j; }
            g_lut[(bh * NBLK + qb) * TSEL + s] = bi;
            sc[bi] = -3.4e38f;
        }
    }
}

// ---------------------------------------------------------------------------
// K3: kv = phi(k)^T v (written pair-interleaved) and z = sum phi(k)
// ---------------------------------------------------------------------------
__global__ void __launch_bounds__(256) k_kvz(const float* __restrict__ k,
                                             const float* __restrict__ v) {
    __shared__ float ck[64 * P68];
    __shared__ float vs[64 * P68];
    int tid = threadIdx.x;
    int bh = blockIdx.x >> 6, kb = blockIdx.x & 63;
    size_t goff = ((size_t)bh * Ll + kb * 64) * Dd;
    int vm = tid >> 4, ve = (tid & 15) * 4;
#pragma unroll
    for (int p = 0; p < 4; p++) {
        int m = vm + p * 16;
        *(float4*)&ck[m * P68 + ve] = *(const float4*)&k[goff + (size_t)m * 64 + ve];
        *(float4*)&vs[m * P68 + ve] = *(const float4*)&v[goff + (size_t)m * 64 + ve];
    }
    __syncthreads();
    int warp = tid >> 5, lane = tid & 31;
    for (int r = warp; r < 64; r += 8) {
        float x0 = ck[r * P68 + lane], x1 = ck[r * P68 + lane + 32];
        float m = fmaxf(x0, x1);
#pragma unroll
        for (int o = 16; o; o >>= 1) m = fmaxf(m, __shfl_xor_sync(~0u, m, o));
        float e0 = __expf(x0 - m), e1 = __expf(x1 - m);
        float s = e0 + e1;
#pragma unroll
        for (int o = 16; o; o >>= 1) s += __shfl_xor_sync(~0u, s, o);
        float inv = 1.f / s;
        ck[r * P68 + lane] = e0 * inv;
        ck[r * P68 + lane + 32] = e1 * inv;
    }
    __syncthreads();
    int tr = tid >> 4, tc = tid & 15;
    ull acc2[8];
#pragma unroll
    for (int i = 0; i < 8; i++) acc2[i] = 0ull;
#pragma unroll 16
    for (int m = 0; m < 64; m++)
        GSTEP(&ck[m * P68 + tr * 4], &vs[m * P68 + tc * 4], acc2);
    // unpack: f[i][j], d = tr*4+i, e = tc*4+j
    float f[4][4];
#pragma unroll
    for (int i = 0; i < 4; i++) {
        float2 c01 = unpk(acc2[i * 2]), c23 = unpk(acc2[i * 2 + 1]);
        f[i][0] = c01.x; f[i][1] = c01.y; f[i][2] = c23.x; f[i][3] = c23.y;
    }
    float* kvout = g_kv + ((size_t)(bh * NBLK + kb)) * Dd * Dd;
#pragma unroll
    for (int j = 0; j < 4; j++) {
        int e = tc * 4 + j;
        *(float2*)&kvout[(2 * tr) * 128 + 2 * e]     = make_float2(f[0][j], f[1][j]);
        *(float2*)&kvout[(2 * tr + 1) * 128 + 2 * e] = make_float2(f[2][j], f[3][j]);
    }
    if (tid < 64) {
        float s = 0.f;
#pragma unroll
        for (int m = 0; m < 64; m++) s += ck[m * P68 + tid];
        g_z[(bh * NBLK + kb) * Dd + tid] = s;
    }
}

// ---------------------------------------------------------------------------
__global__ void k_totals() {
    int bh = blockIdx.x, tid = threadIdx.x;
    int e = blockIdx.y * 256 + tid;
    const float* p = g_kv + (size_t)bh * NBLK * Dd * Dd + e;
    float s = 0.f;
#pragma unroll 8
    for (int kb = 0; kb < NBLK; kb++) s += p[(size_t)kb * Dd * Dd];
    g_kvtot[bh * Dd * Dd + e] = s;
    if (blockIdx.y == 0 && tid < Dd) {
        const float* pz = g_z + bh * NBLK * Dd + tid;
        float sz = 0.f;
#pragma unroll 8
        for (int kb = 0; kb < NBLK; kb++) sz += pz[kb * Dd];
        g_ztot[bh * Dd + tid] = sz;
    }
}

// ---------------------------------------------------------------------------
// K5: fused main kernel. Dot-packed FFMA2 GEMMs (8x2 tile), online softmax.
// smem (floats): Qb 4224 | Kb 4224 | Vb 4224 | Pb 4224 | Nb 4224 | Wb 4224 |
//                zns 64 | bl 64 | den 64  = 25536 fl (~99.8KB), occ 2
// ---------------------------------------------------------------------------
__global__ void __launch_bounds__(256, 2) k_main(
    const float* __restrict__ q, const float* __restrict__ k,
    const float* __restrict__ v, const float* __restrict__ W,
    const float* __restrict__ b, float* __restrict__ out)
{
    extern __shared__ float sm[];
    float* Qb  = sm;            // T2 of Q; later c_q
    float* Kb  = sm + 4224;
    float* Vb  = sm + 8448;
    float* Pb  = sm + 12672;    // T2 P; later T2 o_l
    float* Nb  = sm + 16896;    // T2 kv_ns
    float* Wb  = sm + 21120;
    float* zns = sm + 25344;
    float* bl  = sm + 25408;
    float* den = sm + 25472;
    __shared__ int lut[8];

    int tid = threadIdx.x;
    int bh = blockIdx.x >> 6, qb = blockIdx.x & 63;
    size_t qoff = ((size_t)bh * Ll + qb * 64) * Dd;

    if (tid < TSEL) lut[tid] = g_lut[(bh * NBLK + qb) * TSEL + tid];
    if (tid < 64) bl[tid] = b[tid];

    int dd = tid & 63, rbase = (tid >> 6) * 16;
    int d2s = dd >> 1, hs = dd & 1;

    // stage Q, W into pair-packed layout
    {
        float rq[16], rw[16];
#pragma unroll
        for (int r = 0; r < 16; r++) {
            rq[r] = q[qoff + (size_t)(rbase + r) * 64 + dd];
            rw[r] = W[(rbase + r) * 64 + dd];
        }
#pragma unroll
        for (int r = 0; r < 16; r++) {
            Qb[d2s * PJ + 2 * (rbase + r) + hs] = rq[r];
            Wb[d2s * PJ + 2 * (rbase + r) + hs] = rw[r];
        }
    }

    int tr = tid >> 5;        // 0..7, warp-uniform row group (8 rows)
    int tc = tid & 31;        // 0..31, col pair group (2 cols)

    ull os2[16];              // o_s pair accumulators [ii*2+cc]
    float mrow[8], lrow[8];
#pragma unroll
    for (int i = 0; i < 16; i++) os2[i] = 0ull;
#pragma unroll
    for (int i = 0; i < 8; i++) { mrow[i] = -3.4e38f; lrow[i] = 0.f; }

    for (int t = 0; t < TSEL; t++) {
        __syncthreads();   // prev PV done (and lut/Q visible at t=0)
        // stage K_t (transposed pairs) and V_t (pairs over m)
        {
            size_t ko = ((size_t)bh * Ll + lut[t] * 64) * Dd;
            float rk[16], rv[16];
#pragma unroll
            for (int r = 0; r < 16; r++) {
                rk[r] = k[ko + (size_t)(rbase + r) * 64 + dd];
                rv[r] = v[ko + (size_t)(rbase + r) * 64 + dd];
            }
#pragma unroll
            for (int r = 0; r < 16; r++)
                Kb[d2s * PJ + 2 * (rbase + r) + hs] = rk[r];
#pragma unroll
            for (int r = 0; r < 16; r++) {
                int m = rbase + r;
                Vb[(m >> 1) * PJ + 2 * dd + (m & 1)] = rv[r];
            }
        }
        __syncthreads();

        // ---- S = Q K^T ----
        ull acc[16];
#pragma unroll
        for (int i = 0; i < 16; i++) acc[i] = 0ull;
        DGEMM(Qb, Kb, acc);

        // ---- online softmax (rows 8tr..8tr+7; full-warp reductions) ----
        float pt0[8], pt1[8];
#pragma unroll
        for (int ii = 0; ii < 8; ii++) {
            float2 f0 = unpk(acc[ii * 2]);
            float2 f1 = unpk(acc[ii * 2 + 1]);
            float s0 = (f0.x + f0.y) * SCALE;
            float s1 = (f1.x + f1.y) * SCALE;
            float rm = fmaxf(s0, s1);
#pragma unroll
            for (int o = 16; o; o >>= 1) rm = fmaxf(rm, __shfl_xor_sync(~0u, rm, o));
            float mn = fmaxf(mrow[ii], rm);
            float corr = __expf(mrow[ii] - mn);
            float e0 = __expf(s0 - mn), e1 = __expf(s1 - mn);
            float rs = e0 + e1;
#pragma unroll
            for (int o = 16; o; o >>= 1) rs += __shfl_xor_sync(~0u, rs, o);
            lrow[ii] = lrow[ii] * corr + rs;
            mrow[ii] = mn;
            ull c2 = dup2(corr);
            os2[ii * 2]     = mul2(os2[ii * 2], c2);
            os2[ii * 2 + 1] = mul2(os2[ii * 2 + 1], c2);
            pt0[ii] = e0; pt1[ii] = e1;
        }
        // store P as m-pairs: Pb[tc][2*i + cc]
#pragma unroll
        for (int ii = 0; ii < 8; ii += 2)
            *(float4*)&Pb[tc * PJ + 16 * tr + 2 * ii] =
                make_float4(pt0[ii], pt1[ii], pt0[ii + 1], pt1[ii + 1]);
        __syncthreads();

        // ---- o_s += P V ----
        DGEMM(Pb, Vb, os2);
    }
    __syncthreads();

    // finalize o_s
    float osf[16];
#pragma unroll
    for (int ii = 0; ii < 8; ii++) {
        float invl = 1.f / lrow[ii];
        float2 f0 = unpk(os2[ii * 2]), f1 = unpk(os2[ii * 2 + 1]);
        osf[ii * 2]     = (f0.x + f0.y) * invl;
        osf[ii * 2 + 1] = (f1.x + f1.y) * invl;
    }

    // ---- c_q = softmax over D, in place in Qb (4 threads per row) ----
    {
        int i = tid >> 2, sub = tid & 3;
        float xv[16];
        float mx = -3.4e38f;
#pragma unroll
        for (int s = 0; s < 8; s++) {
            int d2 = sub * 8 + s;
            xv[s * 2]     = Qb[d2 * PJ + 2 * i];
            xv[s * 2 + 1] = Qb[d2 * PJ + 2 * i + 1];
            mx = fmaxf(mx, fmaxf(xv[s * 2], xv[s * 2 + 1]));
        }
        mx = fmaxf(mx, __shfl_xor_sync(~0u, mx, 1));
        mx = fmaxf(mx, __shfl_xor_sync(~0u, mx, 2));
        float ssum = 0.f;
#pragma unroll
        for (int s = 0; s < 16; s++) { xv[s] = __expf(xv[s] - mx); ssum += xv[s]; }
        ssum += __shfl_xor_sync(~0u, ssum, 1);
        ssum += __shfl_xor_sync(~0u, ssum, 2);
        float inv = 1.f / ssum;
#pragma unroll
        for (int s = 0; s < 8; s++) {
            int d2 = sub * 8 + s;
            Qb[d2 * PJ + 2 * i]     = xv[s * 2] * inv;
            Qb[d2 * PJ + 2 * i + 1] = xv[s * 2 + 1] * inv;
        }
    }

    // ---- kv_ns into Nb (pair layout preserved), z_ns ----
    {
        int nd2 = tid >> 3, nc = (tid & 7) * 16;
        const float* kvt = g_kvtot + bh * 4096;
#pragma unroll
        for (int p = 0; p < 4; p++) {
            float4 s = *(const float4*)&kvt[nd2 * 128 + nc + 4 * p];
#pragma unroll
            for (int t = 0; t < TSEL; t++) {
                const float4 x = *(const float4*)
                    &g_kv[((size_t)(bh * NBLK + lut[t])) * 4096 + nd2 * 128 + nc + 4 * p];
                s.x -= x.x; s.y -= x.y; s.z -= x.z; s.w -= x.w;
            }
            *(float4*)&Nb[nd2 * PJ + nc + 4 * p] = s;
        }
        if (tid < 64) {
            float s = g_ztot[bh * Dd + tid];
#pragma unroll
            for (int t = 0; t < TSEL; t++) s -= g_z[(bh * NBLK + lut[t]) * Dd + tid];
            zns[tid] = s;
        }
    }
    __syncthreads();

    // ---- den (4 threads per row) ----
    {
        int i = tid >> 2, sub = tid & 3;
        float ds = 0.f;
#pragma unroll
        for (int s = 0; s < 8; s++) {
            int d2 = sub * 8 + s;
            ds += Qb[d2 * PJ + 2 * i] * zns[2 * d2]
                + Qb[d2 * PJ + 2 * i + 1] * zns[2 * d2 + 1];
        }
        ds += __shfl_xor_sync(~0u, ds, 1);
        ds += __shfl_xor_sync(~0u, ds, 2);
        if (sub == 0) den[i] = ds;
    }
    __syncthreads();

    // ---- o_l = (c_q kv_ns)/den -> Pb (pairs over e) ----
    {
        ull acc[16];
#pragma unroll
        for (int i = 0; i < 16; i++) acc[i] = 0ull;
        DGEMM(Qb, Nb, acc);
        float ol0[8], ol1[8];
#pragma unroll
        for (int ii = 0; ii < 8; ii++) {
            float inv = 1.f / (den[8 * tr + ii] + 1e-6f);
            float2 f0 = unpk(acc[ii * 2]), f1 = unpk(acc[ii * 2 + 1]);
            ol0[ii] = (f0.x + f0.y) * inv;
            ol1[ii] = (f1.x + f1.y) * inv;
        }
        __syncthreads();   // Pb free (last PV long done; also den reads done)
#pragma unroll
        for (int ii = 0; ii < 8; ii += 2)
            *(float4*)&Pb[tc * PJ + 16 * tr + 2 * ii] =
                make_float4(ol0[ii], ol1[ii], ol0[ii + 1], ol1[ii + 1]);
    }
    __syncthreads();

    // ---- out = o_s + o_l W^T + b ----
    {
        ull acc[16];
#pragma unroll
        for (int i = 0; i < 16; i++) acc[i] = 0ull;
        DGEMM(Pb, Wb, acc);
        float2 bv = *(float2*)&bl[tc * 2];
#pragma unroll
        for (int ii = 0; ii < 8; ii++) {
            float2 f0 = unpk(acc[ii * 2]), f1 = unpk(acc[ii * 2 + 1]);
            *(float2*)&out[qoff + (size_t)(8 * tr + ii) * 64 + 2 * tc] =
                make_float2(osf[ii * 2] + f0.x + f0.y + bv.x,
                            osf[ii * 2 + 1] + f1.x + f1.y + bv.y);
        }
    }
}

// ---------------------------------------------------------------------------
extern "C" void kernel_launch(void* const* d_in, const int* in_sizes, int n_in,
                              void* d_out, int out_size) {
    const float* q = (const float*)d_in[0];
    const float* k = (const float*)d_in[1];
    const float* v = (const float*)d_in[2];
    const float* W = (const float*)d_in[3];
    const float* b = (const float*)d_in[4];
    float* out = (float*)d_out;

    int smem_main = 25536 * (int)sizeof(float);
    cudaFuncSetAttribute(k_main, cudaFuncAttributeMaxDynamicSharedMemorySize, smem_main);

    dim3 g1(BH * NBLK, 2);
    k_blockmean<<<g1, 64>>>(q, k);
    k_topk<<<BH * NBLK, 64>>>();
    k_kvz<<<BH * NBLK, 256>>>(k, v);
    k_totals<<<dim3(BH, 16), 256>>>();
    k_main<<<BH * NBLK, 256, smem_main>>>(q, k, v, W, b, out);
}